// round 1
// baseline (speedup 1.0000x reference)
#include <cuda_runtime.h>

#define BB 2048
#define TT 1024
#define DD 32

// One CTA per batch row. Thread t owns timestep t.
// v_0 = init_state; v_t = Wz @ z[b, t-1]  (t >= 1)
// Inclusive affine scan with constant A = Ws:
//   state_t = A^t s0 + sum_k A^{t-k} v_k   == inclusive scan of v with combine
//   x <- A^(len_right) * x_left + x_right  (all powers of A commute)
__global__ __launch_bounds__(1024, 1)
void ar_decoder_kernel(const float* __restrict__ init_states,
                       const float* __restrict__ z,
                       const float* __restrict__ W,
                       float* __restrict__ out) {
    __shared__ float  sW[68];     // W is (2, 34) row-major
    __shared__ float2 agg[32];    // per-warp aggregates

    const int b    = blockIdx.x;
    const int t    = threadIdx.x;
    const int lane = t & 31;
    const int warp = t >> 5;

    if (t < 68) sW[t] = W[t];
    __syncthreads();

    const float a00 = sW[0],  a01 = sW[1];
    const float a10 = sW[34], a11 = sW[35];

    // ---- per-timestep input vector v ----
    float2 v;
    if (t == 0) {
        v.x = init_states[2 * b];
        v.y = init_states[2 * b + 1];
    } else {
        const float4* zp =
            reinterpret_cast<const float4*>(z + ((size_t)b * TT + (t - 1)) * DD);
        float sx = 0.f, sy = 0.f;
        #pragma unroll
        for (int j = 0; j < 8; ++j) {
            float4 q = zp[j];
            sx += q.x * sW[2 + 4 * j + 0] + q.y * sW[2 + 4 * j + 1]
                + q.z * sW[2 + 4 * j + 2] + q.w * sW[2 + 4 * j + 3];
            sy += q.x * sW[36 + 4 * j + 0] + q.y * sW[36 + 4 * j + 1]
                + q.z * sW[36 + 4 * j + 2] + q.w * sW[36 + 4 * j + 3];
        }
        v.x = sx; v.y = sy;
    }

    // ---- phase 1: warp-level inclusive scan (offsets 1,2,4,8,16) ----
    // p tracks A^(2^d); pw* save A^1..A^16 for the per-lane fixup power.
    float p00 = a00, p01 = a01, p10 = a10, p11 = a11;
    float pw0[5], pw1[5], pw2[5], pw3[5];
    #pragma unroll
    for (int d = 0; d < 5; ++d) {
        pw0[d] = p00; pw1[d] = p01; pw2[d] = p10; pw3[d] = p11;
        const int o = 1 << d;
        float ox = __shfl_up_sync(0xffffffffu, v.x, o);
        float oy = __shfl_up_sync(0xffffffffu, v.y, o);
        if (lane >= o) {
            v.x = fmaf(p00, ox, fmaf(p01, oy, v.x));
            v.y = fmaf(p10, ox, fmaf(p11, oy, v.y));
        }
        float q00 = p00 * p00 + p01 * p10;
        float q01 = p00 * p01 + p01 * p11;
        float q10 = p10 * p00 + p11 * p10;
        float q11 = p10 * p01 + p11 * p11;
        p00 = q00; p01 = q01; p10 = q10; p11 = q11;
    }
    // now p = A^32

    if (lane == 31) agg[warp] = v;
    __syncthreads();

    // ---- phase 2: warp 0 scans the 32 warp aggregates (combine power A^(32*o)) ----
    if (warp == 0) {
        float2 x = agg[lane];
        float q00 = p00, q01 = p01, q10 = p10, q11 = p11;  // A^32
        #pragma unroll
        for (int d = 0; d < 5; ++d) {
            const int o = 1 << d;
            float ox = __shfl_up_sync(0xffffffffu, x.x, o);
            float oy = __shfl_up_sync(0xffffffffu, x.y, o);
            if (lane >= o) {
                x.x = fmaf(q00, ox, fmaf(q01, oy, x.x));
                x.y = fmaf(q10, ox, fmaf(q11, oy, x.y));
            }
            float r00 = q00 * q00 + q01 * q10;
            float r01 = q00 * q01 + q01 * q11;
            float r10 = q10 * q00 + q11 * q10;
            float r11 = q10 * q01 + q11 * q11;
            q00 = r00; q01 = r01; q10 = r10; q11 = r11;
        }
        agg[lane] = x;  // inclusive prefix over warps, evaluated at end of warp segment
    }
    __syncthreads();

    // ---- phase 3: fixup — final_t = A^(lane+1) * prefix(warp-1) + local ----
    if (warp > 0) {
        const float2 P = agg[warp - 1];
        const int e = lane + 1;  // 1..32
        float m00 = 1.f, m01 = 0.f, m10 = 0.f, m11 = 1.f;
        #pragma unroll
        for (int d = 0; d < 5; ++d) {
            if (e & (1 << d)) {
                float n00 = pw0[d] * m00 + pw1[d] * m10;
                float n01 = pw0[d] * m01 + pw1[d] * m11;
                float n10 = pw2[d] * m00 + pw3[d] * m10;
                float n11 = pw2[d] * m01 + pw3[d] * m11;
                m00 = n00; m01 = n01; m10 = n10; m11 = n11;
            }
        }
        if (e & 32) { m00 = p00; m01 = p01; m10 = p10; m11 = p11; }  // e == 32 → A^32
        v.x = fmaf(m00, P.x, fmaf(m01, P.y, v.x));
        v.y = fmaf(m10, P.x, fmaf(m11, P.y, v.y));
    }

    // out[b][t][0:2] — consecutive threads write consecutive float2: coalesced.
    reinterpret_cast<float2*>(out)[(size_t)b * TT + t] = v;
}

extern "C" void kernel_launch(void* const* d_in, const int* in_sizes, int n_in,
                              void* d_out, int out_size) {
    const float* init_states = (const float*)d_in[0];
    const float* z           = (const float*)d_in[1];
    const float* W           = (const float*)d_in[2];
    float*       out         = (float*)d_out;
    ar_decoder_kernel<<<BB, TT>>>(init_states, z, W, out);
}

// round 2
// speedup vs baseline: 1.0973x; 1.0973x over previous
#include <cuda_runtime.h>

#define BB 2048
#define TT 1024
#define DD 32

// ======================= Kernel 1: v-compute (streaming) =====================
// out[b,0]   = init_states[b]            (2 floats)
// out[b,t]   = Wz @ z[b,t-1]             (t >= 1)
// One thread per (b,t). Pure stream: 256MB read, 16MB write, no inter-thread deps.
__global__ __launch_bounds__(256)
void vcompute_kernel(const float* __restrict__ init_states,
                     const float* __restrict__ z,
                     const float* __restrict__ W,
                     float* __restrict__ out) {
    __shared__ float4 sWz0[8];   // Wz row 0 (32 floats), 16B-aligned
    __shared__ float4 sWz1[8];   // Wz row 1

    const int idx = blockIdx.x * 256 + threadIdx.x;   // 0 .. B*T-1
    if (threadIdx.x < 64) {
        const int r = threadIdx.x >> 5, c = threadIdx.x & 31;
        float w = W[r * 34 + 2 + c];
        reinterpret_cast<float*>(r ? sWz1 : sWz0)[c] = w;
    }
    __syncthreads();

    const int t = idx & (TT - 1);
    float2 o;
    if (t == 0) {
        const int b = idx >> 10;
        o.x = init_states[2 * b];
        o.y = init_states[2 * b + 1];
    } else {
        // z[b, t-1] flattened = (idx-1) * 32 floats
        const float4* zp = reinterpret_cast<const float4*>(z) + (size_t)(idx - 1) * 8;
        float sx = 0.f, sy = 0.f;
        #pragma unroll
        for (int j = 0; j < 8; ++j) {
            const float4 q  = zp[j];
            const float4 w0 = sWz0[j];
            const float4 w1 = sWz1[j];
            sx = fmaf(q.x, w0.x, fmaf(q.y, w0.y, fmaf(q.z, w0.z, fmaf(q.w, w0.w, sx))));
            sy = fmaf(q.x, w1.x, fmaf(q.y, w1.y, fmaf(q.z, w1.z, fmaf(q.w, w1.w, sy))));
        }
        o.x = sx; o.y = sy;
    }
    reinterpret_cast<float2*>(out)[idx] = o;
}

// ========================= Kernel 2: affine scan =============================
// In-place inclusive scan over out[b, :] with combine x <- A^len * x_left + x.
// Thread-uniform powers A^(2^d) live in shared (not regs) -> ~24 regs -> 2 CTA/SM.
__global__ __launch_bounds__(1024, 2)
void scan_kernel(const float* __restrict__ W,
                 float* __restrict__ out) {
    __shared__ float2 agg[32];
    __shared__ float  sPW[5][4];   // A^1, A^2, A^4, A^8, A^16 (thread-uniform)

    const int b    = blockIdx.x;
    const int t    = threadIdx.x;
    const int lane = t & 31;
    const int warp = t >> 5;

    float2* row = reinterpret_cast<float2*>(out) + (size_t)b * TT;
    float2 v = row[t];

    // A = Ws (uniform loads, L1-cached broadcast)
    float p00 = __ldg(&W[0]),  p01 = __ldg(&W[1]);
    float p10 = __ldg(&W[34]), p11 = __ldg(&W[35]);

    // ---- phase 1: warp inclusive scan; squares the power each step ----
    #pragma unroll
    for (int d = 0; d < 5; ++d) {
        if (t == 0) { sPW[d][0] = p00; sPW[d][1] = p01; sPW[d][2] = p10; sPW[d][3] = p11; }
        const int o = 1 << d;
        float ox = __shfl_up_sync(0xffffffffu, v.x, o);
        float oy = __shfl_up_sync(0xffffffffu, v.y, o);
        if (lane >= o) {
            v.x = fmaf(p00, ox, fmaf(p01, oy, v.x));
            v.y = fmaf(p10, ox, fmaf(p11, oy, v.y));
        }
        float q00 = p00 * p00 + p01 * p10;
        float q01 = p00 * p01 + p01 * p11;
        float q10 = p10 * p00 + p11 * p10;
        float q11 = p10 * p01 + p11 * p11;
        p00 = q00; p01 = q01; p10 = q10; p11 = q11;
    }
    // p = A^32 now

    if (lane == 31) agg[warp] = v;
    __syncthreads();   // also publishes sPW

    // ---- phase 2: warp 0 scans the 32 warp aggregates (powers A^(32*2^d)) ----
    if (warp == 0) {
        float2 x = agg[lane];
        float q00 = p00, q01 = p01, q10 = p10, q11 = p11;
        #pragma unroll
        for (int d = 0; d < 5; ++d) {
            const int o = 1 << d;
            float ox = __shfl_up_sync(0xffffffffu, x.x, o);
            float oy = __shfl_up_sync(0xffffffffu, x.y, o);
            if (lane >= o) {
                x.x = fmaf(q00, ox, fmaf(q01, oy, x.x));
                x.y = fmaf(q10, ox, fmaf(q11, oy, x.y));
            }
            float r00 = q00 * q00 + q01 * q10;
            float r01 = q00 * q01 + q01 * q11;
            float r10 = q10 * q00 + q11 * q10;
            float r11 = q10 * q01 + q11 * q11;
            q00 = r00; q01 = r01; q10 = r10; q11 = r11;
        }
        agg[lane] = x;
    }
    __syncthreads();

    // ---- phase 3: fixup with A^(lane+1) from shared powers ----
    if (warp > 0) {
        const float2 P = agg[warp - 1];
        const int e = lane + 1;   // 1..32
        float m00 = 1.f, m01 = 0.f, m10 = 0.f, m11 = 1.f;
        #pragma unroll
        for (int d = 0; d < 5; ++d) {
            if (e & (1 << d)) {
                const float w0 = sPW[d][0], w1 = sPW[d][1];
                const float w2 = sPW[d][2], w3 = sPW[d][3];
                float n00 = w0 * m00 + w1 * m10;
                float n01 = w0 * m01 + w1 * m11;
                float n10 = w2 * m00 + w3 * m10;
                float n11 = w2 * m01 + w3 * m11;
                m00 = n00; m01 = n01; m10 = n10; m11 = n11;
            }
        }
        if (e & 32) { m00 = p00; m01 = p01; m10 = p10; m11 = p11; }  // e==32 -> A^32
        v.x = fmaf(m00, P.x, fmaf(m01, P.y, v.x));
        v.y = fmaf(m10, P.x, fmaf(m11, P.y, v.y));
    }

    row[t] = v;
}

extern "C" void kernel_launch(void* const* d_in, const int* in_sizes, int n_in,
                              void* d_out, int out_size) {
    const float* init_states = (const float*)d_in[0];
    const float* z           = (const float*)d_in[1];
    const float* W           = (const float*)d_in[2];
    float*       out         = (float*)d_out;

    vcompute_kernel<<<(BB * TT) / 256, 256>>>(init_states, z, W, out);
    scan_kernel<<<BB, 1024>>>(W, out);
}

// round 3
// speedup vs baseline: 1.7140x; 1.5621x over previous
#include <cuda_runtime.h>

#define BB 2048
#define TT 1024

// ======================= Kernel 1: v-compute (coalesced) =====================
// For every z row r (0..B*T-1): out[r+1] = Wz @ z[r], skipped when (r+1)%T==0.
// 8 lanes cooperate per row: lane loads one float4 (warp load = 512B contiguous),
// butterfly-reduce over the 8-lane group, group leaders store coalesced float2s.
__global__ __launch_bounds__(256)
void vcompute_kernel(const float* __restrict__ z,
                     const float* __restrict__ W,
                     float* __restrict__ out) {
    __shared__ float4 sW0[8], sW1[8];
    const int tid = threadIdx.x;
    if (tid < 64) {
        const int rr = tid >> 5, c = tid & 31;
        reinterpret_cast<float*>(rr ? sW1 : sW0)[c] = W[rr * 34 + 2 + c];
    }
    __syncthreads();

    const int lane = tid & 31;
    const int warp = tid >> 5;
    const int g    = lane >> 3;   // row within the 4-row instruction group
    const int c8   = lane & 7;    // column-slice 0..7 (16B each)

    const float4 w0 = sW0[c8];
    const float4 w1 = sW1[c8];

    const long R = ((long)blockIdx.x * 8 + warp) * 32;   // first z row of warp
    float2* out2 = reinterpret_cast<float2*>(out);
    const float4* z4 = reinterpret_cast<const float4*>(z);

    #pragma unroll
    for (int j = 0; j < 8; ++j) {
        const long r = R + j * 4 + g;
        const float4 q = z4[r * 8 + c8];
        float px = fmaf(q.x, w0.x, fmaf(q.y, w0.y, fmaf(q.z, w0.z, q.w * w0.w)));
        float py = fmaf(q.x, w1.x, fmaf(q.y, w1.y, fmaf(q.z, w1.z, q.w * w1.w)));
        #pragma unroll
        for (int o = 1; o < 8; o <<= 1) {
            px += __shfl_xor_sync(0xffffffffu, px, o);
            py += __shfl_xor_sync(0xffffffffu, py, o);
        }
        if (c8 == 0 && ((r + 1) & (TT - 1)) != 0) {
            out2[r + 1] = make_float2(px, py);   // lanes 0,8,16,24: 32B coalesced
        }
    }
}

// ========================= Kernel 2: chunked affine scan =====================
// One row per 128-thread block; each thread owns 8 consecutive timesteps.
// final_pos = s_k + A^(k+1) * (E + A^(lane*8) * P_warp)
__global__ __launch_bounds__(128)
void scan_kernel(const float* __restrict__ init_states,
                 const float* __restrict__ W,
                 float* __restrict__ out) {
    __shared__ float2 agg[4];
    const int b    = blockIdx.x;
    const int tid  = threadIdx.x;
    const int lane = tid & 31;
    const int warp = tid >> 5;

    float2* row = reinterpret_cast<float2*>(out) + (size_t)b * TT;
    float4* rp  = reinterpret_cast<float4*>(row) + tid * 4;

    float4 c0 = rp[0], c1 = rp[1], c2 = rp[2], c3 = rp[3];
    float2 v[8] = { {c0.x,c0.y},{c0.z,c0.w},{c1.x,c1.y},{c1.z,c1.w},
                    {c2.x,c2.y},{c2.z,c2.w},{c3.x,c3.y},{c3.z,c3.w} };
    if (tid == 0) { v[0].x = init_states[2*b]; v[0].y = init_states[2*b+1]; }

    const float a00 = __ldg(&W[0]),  a01 = __ldg(&W[1]);
    const float a10 = __ldg(&W[34]), a11 = __ldg(&W[35]);

    // ---- serial inclusive scan of the chunk ----
    float2 sv[8];
    float2 s = v[0];
    sv[0] = s;
    #pragma unroll
    for (int k = 1; k < 8; ++k) {
        float nx = fmaf(a00, s.x, fmaf(a01, s.y, v[k].x));
        float ny = fmaf(a10, s.x, fmaf(a11, s.y, v[k].y));
        s.x = nx; s.y = ny;
        sv[k] = s;
    }

    // ---- powers: A -> A^8 (3 squarings) ----
    float p00=a00,p01=a01,p10=a10,p11=a11;
    #pragma unroll
    for (int i = 0; i < 3; ++i) {
        float q00=p00*p00+p01*p10, q01=p00*p01+p01*p11;
        float q10=p10*p00+p11*p10, q11=p10*p01+p11*p11;
        p00=q00;p01=q01;p10=q10;p11=q11;
    }

    // ---- warp shuffle scan of aggregates, powers A^(8*2^d) ----
    float S0[5],S1[5],S2[5],S3[5];
    float2 x = s;
    #pragma unroll
    for (int d = 0; d < 5; ++d) {
        S0[d]=p00; S1[d]=p01; S2[d]=p10; S3[d]=p11;
        const int o = 1 << d;
        float ox = __shfl_up_sync(0xffffffffu, x.x, o);
        float oy = __shfl_up_sync(0xffffffffu, x.y, o);
        if (lane >= o) {
            x.x = fmaf(p00, ox, fmaf(p01, oy, x.x));
            x.y = fmaf(p10, ox, fmaf(p11, oy, x.y));
        }
        float q00=p00*p00+p01*p10, q01=p00*p01+p01*p11;
        float q10=p10*p00+p11*p10, q11=p10*p01+p11*p11;
        p00=q00;p01=q01;p10=q10;p11=q11;
    }
    // p = A^256 (one warp segment)

    if (lane == 31) agg[warp] = x;
    __syncthreads();

    // ---- prefix over earlier warps: P = scan(agg[0..warp-1]) with A^256 ----
    float2 P = make_float2(0.f, 0.f);
    for (int u = 0; u < warp; ++u) {
        float nx = fmaf(p00, P.x, fmaf(p01, P.y, agg[u].x));
        float ny = fmaf(p10, P.x, fmaf(p11, P.y, agg[u].y));
        P.x = nx; P.y = ny;
    }

    // ---- exclusive lane prefix ----
    float Ex = __shfl_up_sync(0xffffffffu, x.x, 1);
    float Ey = __shfl_up_sync(0xffffffffu, x.y, 1);
    if (lane == 0) { Ex = 0.f; Ey = 0.f; }

    // ---- M = A^(lane*8) from saved squaring chain ----
    float m00=1.f,m01=0.f,m10=0.f,m11=1.f;
    #pragma unroll
    for (int d = 0; d < 5; ++d) {
        if (lane & (1 << d)) {
            float n00=S0[d]*m00+S1[d]*m10, n01=S0[d]*m01+S1[d]*m11;
            float n10=S2[d]*m00+S3[d]*m10, n11=S2[d]*m01+S3[d]*m11;
            m00=n00;m01=n01;m10=n10;m11=n11;
        }
    }
    float bx = Ex + m00 * P.x + m01 * P.y;
    float by = Ey + m10 * P.x + m11 * P.y;

    // ---- fused carry fixup + store ----
    float cx = fmaf(a00, bx, a01 * by);
    float cy = fmaf(a10, bx, a11 * by);
    float2 y[8];
    #pragma unroll
    for (int k = 0; k < 8; ++k) {
        y[k].x = sv[k].x + cx;
        y[k].y = sv[k].y + cy;
        float nx = fmaf(a00, cx, a01 * cy);
        float ny = fmaf(a10, cx, a11 * cy);
        cx = nx; cy = ny;
    }
    rp[0] = make_float4(y[0].x, y[0].y, y[1].x, y[1].y);
    rp[1] = make_float4(y[2].x, y[2].y, y[3].x, y[3].y);
    rp[2] = make_float4(y[4].x, y[4].y, y[5].x, y[5].y);
    rp[3] = make_float4(y[6].x, y[6].y, y[7].x, y[7].y);
}

extern "C" void kernel_launch(void* const* d_in, const int* in_sizes, int n_in,
                              void* d_out, int out_size) {
    const float* init_states = (const float*)d_in[0];
    const float* z           = (const float*)d_in[1];
    const float* W           = (const float*)d_in[2];
    float*       out         = (float*)d_out;

    vcompute_kernel<<<(BB * TT) / 256, 256>>>(z, W, out);
    scan_kernel<<<BB, 128>>>(init_states, W, out);
}

// round 4
// speedup vs baseline: 1.7671x; 1.0310x over previous
#include <cuda_runtime.h>

#define BB 2048
#define TT 1024

// ============================ Fused decoder ================================
// One CTA (256 threads) per batch row b.
// Phase A: v[t] = Wz @ z[b,t-1]  (t>=1), v[0] = init_states[b]  -> shared mem
//   8 lanes cooperate per z row; warp load = 512B contiguous; butterfly reduce.
// Phase B: chunked affine scan (4 timesteps/thread) with combine
//   x <- A^len * x_left + x  (A = Ws, constant), coalesced float4 stores.
__global__ __launch_bounds__(256)
void fused_decoder_kernel(const float* __restrict__ init_states,
                          const float* __restrict__ z,
                          const float* __restrict__ W,
                          float* __restrict__ out) {
    __shared__ alignas(16) float2 sv[TT];   // 8KB: per-timestep input vectors
    __shared__ float2 agg[8];               // per-warp scan aggregates
    __shared__ float  sPW[5][4];            // A^4, A^8, A^16, A^32, A^64
    __shared__ float4 sW0[8], sW1[8];       // Wz rows

    const int b    = blockIdx.x;
    const int tid  = threadIdx.x;
    const int lane = tid & 31;
    const int warp = tid >> 5;

    if (tid < 64) {
        const int rr = tid >> 5, c = tid & 31;
        reinterpret_cast<float*>(rr ? sW1 : sW0)[c] = W[rr * 34 + 2 + c];
    }
    __syncthreads();

    // ---------------- Phase A: dot products into shared ----------------
    {
        const int g  = lane >> 3;   // row within 4-row group
        const int c8 = lane & 7;    // 16B column slice
        const float4 w0 = sW0[c8];
        const float4 w1 = sW1[c8];
        const float4* z4 = reinterpret_cast<const float4*>(z) + (size_t)b * TT * 8;
        const int base = warp * 128;   // each warp owns 128 consecutive z rows

        #pragma unroll 8
        for (int j = 0; j < 32; ++j) {
            const int r = base + j * 4 + g;
            const float4 q = z4[r * 8 + c8];
            float px = fmaf(q.x, w0.x, fmaf(q.y, w0.y, fmaf(q.z, w0.z, q.w * w0.w)));
            float py = fmaf(q.x, w1.x, fmaf(q.y, w1.y, fmaf(q.z, w1.z, q.w * w1.w)));
            #pragma unroll
            for (int o = 1; o < 8; o <<= 1) {
                px += __shfl_xor_sync(0xffffffffu, px, o);
                py += __shfl_xor_sync(0xffffffffu, py, o);
            }
            if (c8 == 0 && r + 1 < TT) sv[r + 1] = make_float2(px, py);
        }
    }
    if (tid == 0) sv[0] = make_float2(init_states[2 * b], init_states[2 * b + 1]);
    __syncthreads();

    // ---------------- Phase B: chunked affine scan ----------------
    const float a00 = __ldg(&W[0]),  a01 = __ldg(&W[1]);
    const float a10 = __ldg(&W[34]), a11 = __ldg(&W[35]);

    // thread's 4 consecutive timesteps from shared
    const float4* svp = reinterpret_cast<const float4*>(sv) + tid * 2;
    const float4 c0 = svp[0], c1 = svp[1];
    float2 v[4] = { {c0.x, c0.y}, {c0.z, c0.w}, {c1.x, c1.y}, {c1.z, c1.w} };

    // serial inclusive scan of the 4-chunk
    float2 svl[4];
    float2 s = v[0];
    svl[0] = s;
    #pragma unroll
    for (int k = 1; k < 4; ++k) {
        float nx = fmaf(a00, s.x, fmaf(a01, s.y, v[k].x));
        float ny = fmaf(a10, s.x, fmaf(a11, s.y, v[k].y));
        s.x = nx; s.y = ny;
        svl[k] = s;
    }

    // A -> A^4 (2 squarings)
    float p00 = a00, p01 = a01, p10 = a10, p11 = a11;
    #pragma unroll
    for (int i = 0; i < 2; ++i) {
        float q00 = p00*p00 + p01*p10, q01 = p00*p01 + p01*p11;
        float q10 = p10*p00 + p11*p10, q11 = p10*p01 + p11*p11;
        p00 = q00; p01 = q01; p10 = q10; p11 = q11;
    }

    // warp shuffle scan of chunk aggregates; powers A^(4*2^d)
    float2 x = s;
    #pragma unroll
    for (int d = 0; d < 5; ++d) {
        if (tid == 0) { sPW[d][0] = p00; sPW[d][1] = p01; sPW[d][2] = p10; sPW[d][3] = p11; }
        const int o = 1 << d;
        float ox = __shfl_up_sync(0xffffffffu, x.x, o);
        float oy = __shfl_up_sync(0xffffffffu, x.y, o);
        if (lane >= o) {
            x.x = fmaf(p00, ox, fmaf(p01, oy, x.x));
            x.y = fmaf(p10, ox, fmaf(p11, oy, x.y));
        }
        float q00 = p00*p00 + p01*p10, q01 = p00*p01 + p01*p11;
        float q10 = p10*p00 + p11*p10, q11 = p10*p01 + p11*p11;
        p00 = q00; p01 = q01; p10 = q10; p11 = q11;
    }
    // p = A^128 (one warp segment = 32 lanes * 4)

    if (lane == 31) agg[warp] = x;
    __syncthreads();   // publishes agg and sPW

    // prefix over earlier warps (combine power A^128), <=7 serial steps
    float2 P = make_float2(0.f, 0.f);
    for (int u = 0; u < warp; ++u) {
        float nx = fmaf(p00, P.x, fmaf(p01, P.y, agg[u].x));
        float ny = fmaf(p10, P.x, fmaf(p11, P.y, agg[u].y));
        P.x = nx; P.y = ny;
    }

    // exclusive lane prefix within warp
    float Ex = __shfl_up_sync(0xffffffffu, x.x, 1);
    float Ey = __shfl_up_sync(0xffffffffu, x.y, 1);
    if (lane == 0) { Ex = 0.f; Ey = 0.f; }

    // M = A^(4*lane) from shared power table
    float m00 = 1.f, m01 = 0.f, m10 = 0.f, m11 = 1.f;
    #pragma unroll
    for (int d = 0; d < 5; ++d) {
        if (lane & (1 << d)) {
            const float w0 = sPW[d][0], w1 = sPW[d][1];
            const float w2 = sPW[d][2], w3 = sPW[d][3];
            float n00 = w0*m00 + w1*m10, n01 = w0*m01 + w1*m11;
            float n10 = w2*m00 + w3*m10, n11 = w2*m01 + w3*m11;
            m00 = n00; m01 = n01; m10 = n10; m11 = n11;
        }
    }
    float bx = Ex + m00 * P.x + m01 * P.y;
    float by = Ey + m10 * P.x + m11 * P.y;

    // carry fixup + coalesced store
    float cx = fmaf(a00, bx, a01 * by);
    float cy = fmaf(a10, bx, a11 * by);
    float2 y[4];
    #pragma unroll
    for (int k = 0; k < 4; ++k) {
        y[k].x = svl[k].x + cx;
        y[k].y = svl[k].y + cy;
        float nx = fmaf(a00, cx, a01 * cy);
        float ny = fmaf(a10, cx, a11 * cy);
        cx = nx; cy = ny;
    }
    float4* op = reinterpret_cast<float4*>(out) + ((size_t)b * TT / 2) + tid * 2;
    op[0] = make_float4(y[0].x, y[0].y, y[1].x, y[1].y);
    op[1] = make_float4(y[2].x, y[2].y, y[3].x, y[3].y);
}

extern "C" void kernel_launch(void* const* d_in, const int* in_sizes, int n_in,
                              void* d_out, int out_size) {
    const float* init_states = (const float*)d_in[0];
    const float* z           = (const float*)d_in[1];
    const float* W           = (const float*)d_in[2];
    float*       out         = (float*)d_out;

    fused_decoder_kernel<<<BB, 256>>>(init_states, z, W, out);
}